// round 1
// baseline (speedup 1.0000x reference)
#include <cuda_runtime.h>

#define T 48
#define E 32
#define C0 64
#define C1 64
#define H1 256
#define H2 128
#define NPRED 12
#define SEQS (16 * 2048)

// scratch: attention context last row per sequence
__device__ float g_last[SEQS * C1];

// ---------------- Kernel A: in-proj + conv + k/v + last-row attention ----------------
// smem layout (float offsets):
//  sWin   @ 0      (2048)
//  sWc    @ 2048   (12288)
//  sWq    @ 14336  (4096)
//  sWk    @ 18432  (4096)
//  sWv    @ 22528  (4096)
//  sB     @ 26624  (320)  : bin, bc, bq, bk, bv (64 each)
//  sx     @ 26944  (1536)
//  sh     @ 28480  (3200) : padded (T+2) x 64, rows 0 and 49 are zero
//  shc    @ 31680  (3072)
//  sk     @ 34752  (3072)
//  sv     @ 37824  (3072)
//  sq     @ 40896  (64)
//  ss     @ 40960  (64)
// total 41024 floats = 164096 bytes
#define SMEM_A_FLOATS 41024

__global__ void __launch_bounds__(256, 1)
kernelA(const float* __restrict__ x,
        const float* __restrict__ Win, const float* __restrict__ bin,
        const float* __restrict__ Wc,  const float* __restrict__ bc,
        const float* __restrict__ Wq,  const float* __restrict__ bq,
        const float* __restrict__ Wk,  const float* __restrict__ bk,
        const float* __restrict__ Wv,  const float* __restrict__ bv)
{
    extern __shared__ float sm[];
    float* sWin = sm;
    float* sWc  = sm + 2048;
    float* sWq  = sm + 14336;
    float* sWk  = sm + 18432;
    float* sWv  = sm + 22528;
    float* sB   = sm + 26624;
    float* sx   = sm + 26944;
    float* sh   = sm + 28480;
    float* shc  = sm + 31680;
    float* sk   = sm + 34752;
    float* sv   = sm + 37824;
    float* sq   = sm + 40896;
    float* ss   = sm + 40960;

    const int tid = threadIdx.x;

    // stage weights once per CTA
    for (int i = tid; i < 2048; i += 256) sWin[i] = Win[i];
    for (int i = tid; i < 12288; i += 256) sWc[i] = Wc[i];
    for (int i = tid; i < 4096; i += 256) {
        sWq[i] = Wq[i]; sWk[i] = Wk[i]; sWv[i] = Wv[i];
    }
    if (tid < 64) {
        sB[tid]       = bin[tid];
        sB[64 + tid]  = bc[tid];
        sB[128 + tid] = bq[tid];
        sB[192 + tid] = bk[tid];
        sB[256 + tid] = bv[tid];
        sh[tid] = 0.f;              // pad row t = -1
        sh[49 * 64 + tid] = 0.f;    // pad row t = T
    }
    __syncthreads();

    const int tw   = tid >> 4;   // 0..15 : t in {tw, tw+16, tw+32}
    const int c4   = tid & 15;   // c = 4*c4
    const int lane = tid & 31;
    const int warp = tid >> 5;

    for (int seq = blockIdx.x; seq < SEQS; seq += gridDim.x) {
        // ---- 1) load x tile ----
        const float4* xg = (const float4*)(x + (size_t)seq * (T * E));
        float4* sx4 = (float4*)sx;
        for (int i = tid; i < (T * E) / 4; i += 256) sx4[i] = xg[i];
        __syncthreads();

        // ---- 2) in-projection: h[t][c] = x[t]·Win[:,c] + bin ----
        {
            float4 b4 = ((const float4*)sB)[c4];
            float acc[3][4];
            #pragma unroll
            for (int j = 0; j < 3; j++) {
                acc[j][0] = b4.x; acc[j][1] = b4.y; acc[j][2] = b4.z; acc[j][3] = b4.w;
            }
            #pragma unroll
            for (int e = 0; e < E; e++) {
                float4 w = ((const float4*)(sWin + e * C0))[c4];
                float xv[3];
                #pragma unroll
                for (int j = 0; j < 3; j++) xv[j] = sx[(tw + 16 * j) * E + e];
                #pragma unroll
                for (int j = 0; j < 3; j++) {
                    acc[j][0] += xv[j] * w.x; acc[j][1] += xv[j] * w.y;
                    acc[j][2] += xv[j] * w.z; acc[j][3] += xv[j] * w.w;
                }
            }
            #pragma unroll
            for (int j = 0; j < 3; j++) {
                int row = tw + 16 * j + 1;
                ((float4*)(sh + row * C0))[c4] =
                    make_float4(acc[j][0], acc[j][1], acc[j][2], acc[j][3]);
            }
        }
        __syncthreads();

        // ---- 3) conv(k=3, pad=1) + ReLU ----
        {
            float4 b4 = ((const float4*)(sB + 64))[c4];
            float acc[3][4];
            #pragma unroll
            for (int j = 0; j < 3; j++) {
                acc[j][0] = b4.x; acc[j][1] = b4.y; acc[j][2] = b4.z; acc[j][3] = b4.w;
            }
            #pragma unroll
            for (int dt = 0; dt < 3; dt++) {
                const float* wb = sWc + dt * C0 * C1;
                const float* hb = sh + dt * C0;   // padded row index t+dt
                #pragma unroll 8
                for (int ci = 0; ci < C0; ci++) {
                    float4 w = ((const float4*)(wb + ci * C1))[c4];
                    float hv[3];
                    #pragma unroll
                    for (int j = 0; j < 3; j++) hv[j] = hb[(tw + 16 * j) * C0 + ci];
                    #pragma unroll
                    for (int j = 0; j < 3; j++) {
                        acc[j][0] += hv[j] * w.x; acc[j][1] += hv[j] * w.y;
                        acc[j][2] += hv[j] * w.z; acc[j][3] += hv[j] * w.w;
                    }
                }
            }
            #pragma unroll
            for (int j = 0; j < 3; j++) {
                int row = tw + 16 * j;
                ((float4*)(shc + row * C1))[c4] =
                    make_float4(fmaxf(acc[j][0], 0.f), fmaxf(acc[j][1], 0.f),
                                fmaxf(acc[j][2], 0.f), fmaxf(acc[j][3], 0.f));
            }
        }
        __syncthreads();

        // ---- 4) k & v projections (fused), plus q for last row ----
        {
            float4 bk4 = ((const float4*)(sB + 192))[c4];
            float4 bv4 = ((const float4*)(sB + 256))[c4];
            float ak[3][4], av[3][4];
            #pragma unroll
            for (int j = 0; j < 3; j++) {
                ak[j][0] = bk4.x; ak[j][1] = bk4.y; ak[j][2] = bk4.z; ak[j][3] = bk4.w;
                av[j][0] = bv4.x; av[j][1] = bv4.y; av[j][2] = bv4.z; av[j][3] = bv4.w;
            }
            #pragma unroll 8
            for (int ci = 0; ci < C1; ci++) {
                float4 wk4 = ((const float4*)(sWk + ci * C1))[c4];
                float4 wv4 = ((const float4*)(sWv + ci * C1))[c4];
                float hv[3];
                #pragma unroll
                for (int j = 0; j < 3; j++) hv[j] = shc[(tw + 16 * j) * C1 + ci];
                #pragma unroll
                for (int j = 0; j < 3; j++) {
                    ak[j][0] += hv[j] * wk4.x; ak[j][1] += hv[j] * wk4.y;
                    ak[j][2] += hv[j] * wk4.z; ak[j][3] += hv[j] * wk4.w;
                    av[j][0] += hv[j] * wv4.x; av[j][1] += hv[j] * wv4.y;
                    av[j][2] += hv[j] * wv4.z; av[j][3] += hv[j] * wv4.w;
                }
            }
            #pragma unroll
            for (int j = 0; j < 3; j++) {
                int row = tw + 16 * j;
                ((float4*)(sk + row * C1))[c4] =
                    make_float4(ak[j][0], ak[j][1], ak[j][2], ak[j][3]);
                ((float4*)(sv + row * C1))[c4] =
                    make_float4(av[j][0], av[j][1], av[j][2], av[j][3]);
            }
        }
        if (tid < 64) {  // q for t = T-1 only
            float a = sB[128 + tid];
            #pragma unroll 8
            for (int ci = 0; ci < C1; ci++) a += shc[47 * C1 + ci] * sWq[ci * C1 + tid];
            sq[tid] = a;
        }
        __syncthreads();

        // ---- 5) scores[t] = q · k[t] / 8   (each warp handles 6 t) ----
        #pragma unroll
        for (int jj = 0; jj < 6; jj++) {
            int t = warp * 6 + jj;
            float p = sq[lane] * sk[t * C1 + lane] + sq[lane + 32] * sk[t * C1 + lane + 32];
            #pragma unroll
            for (int o = 16; o > 0; o >>= 1) p += __shfl_xor_sync(0xffffffffu, p, o);
            if (lane == 0) ss[t] = p * 0.125f;
        }
        __syncthreads();

        // ---- 6) softmax over 48 (warp 0) ----
        if (warp == 0) {
            float a  = ss[lane];
            float b2 = (lane < 16) ? ss[lane + 32] : -1e30f;
            float m = fmaxf(a, b2);
            #pragma unroll
            for (int o = 16; o > 0; o >>= 1) m = fmaxf(m, __shfl_xor_sync(0xffffffffu, m, o));
            float ea = __expf(a - m);
            float eb = (lane < 16) ? __expf(b2 - m) : 0.f;
            float s = ea + eb;
            #pragma unroll
            for (int o = 16; o > 0; o >>= 1) s += __shfl_xor_sync(0xffffffffu, s, o);
            float inv = 1.f / s;
            ss[lane] = ea * inv;
            if (lane < 16) ss[lane + 32] = eb * inv;
        }
        __syncthreads();

        // ---- 7) ctx = attn · v  →  g_last ----
        if (tid < 64) {
            float a = 0.f;
            #pragma unroll
            for (int t = 0; t < T; t++) a += ss[t] * sv[t * C1 + tid];
            g_last[(size_t)seq * C1 + tid] = a;
        }
        __syncthreads();
    }
}

// ---------------- Kernel B: MLP 64 -> 256 -> 128 -> 12, transposed write ----------------
// smem: sW1@0(16384) sW2@16384(32768) sW3@49152(1536) sb1@50688(256)
//       sb2@50944(128) sb3@51072(16) sIn@51088(512) sZ1@51600(2048) sZ2@53648(1024)
// total 54672 floats = 218688 bytes
#define SMEM_B_FLOATS 54672

__global__ void __launch_bounds__(256, 1)
kernelB(const float* __restrict__ W1, const float* __restrict__ b1,
        const float* __restrict__ W2, const float* __restrict__ b2,
        const float* __restrict__ W3, const float* __restrict__ b3,
        float* __restrict__ out)
{
    extern __shared__ float sm[];
    float* sW1 = sm;
    float* sW2 = sm + 16384;
    float* sW3 = sm + 49152;
    float* sb1 = sm + 50688;
    float* sb2 = sm + 50944;
    float* sb3 = sm + 51072;
    float* sIn = sm + 51088;
    float* sZ1 = sm + 51600;
    float* sZ2 = sm + 53648;

    const int tid = threadIdx.x;

    for (int i = tid; i < 16384; i += 256) sW1[i] = W1[i];
    for (int i = tid; i < 32768; i += 256) sW2[i] = W2[i];
    for (int i = tid; i < 1536; i += 256) sW3[i] = W3[i];
    if (tid < 256) sb1[tid] = b1[tid];
    if (tid < 128) sb2[tid] = b2[tid];
    if (tid < 12)  sb3[tid] = b3[tid];
    __syncthreads();

    for (int base = blockIdx.x * 8; base < SEQS; base += gridDim.x * 8) {
        // load 8 rows of g_last
        {
            const float4* src = (const float4*)(g_last + (size_t)base * C1);
            float4* dst = (float4*)sIn;
            for (int i = tid; i < 128; i += 256) dst[i] = src[i];
        }
        __syncthreads();

        // z1 = relu(in @ W1 + b1) : [8][256]
        {
            int c64 = tid & 63;   // co = 4*c64
            int rr  = tid >> 6;   // rows rr, rr+4
            float4 bb = ((const float4*)sb1)[c64];
            float a0[4] = {bb.x, bb.y, bb.z, bb.w};
            float a1[4] = {bb.x, bb.y, bb.z, bb.w};
            #pragma unroll 8
            for (int f = 0; f < 64; f++) {
                float4 w = ((const float4*)(sW1 + f * H1))[c64];
                float x0 = sIn[rr * 64 + f];
                float x1 = sIn[(rr + 4) * 64 + f];
                a0[0] += x0 * w.x; a0[1] += x0 * w.y; a0[2] += x0 * w.z; a0[3] += x0 * w.w;
                a1[0] += x1 * w.x; a1[1] += x1 * w.y; a1[2] += x1 * w.z; a1[3] += x1 * w.w;
            }
            ((float4*)(sZ1 + rr * H1))[c64] =
                make_float4(fmaxf(a0[0], 0.f), fmaxf(a0[1], 0.f), fmaxf(a0[2], 0.f), fmaxf(a0[3], 0.f));
            ((float4*)(sZ1 + (rr + 4) * H1))[c64] =
                make_float4(fmaxf(a1[0], 0.f), fmaxf(a1[1], 0.f), fmaxf(a1[2], 0.f), fmaxf(a1[3], 0.f));
        }
        __syncthreads();

        // z2 = relu(z1 @ W2 + b2) : [8][128]
        {
            int c32 = tid & 31;   // co = 4*c32
            int r   = tid >> 5;   // 0..7
            float4 bb = ((const float4*)sb2)[c32];
            float a[4] = {bb.x, bb.y, bb.z, bb.w};
            #pragma unroll 8
            for (int f = 0; f < 256; f++) {
                float4 w = ((const float4*)(sW2 + f * H2))[c32];
                float z = sZ1[r * H1 + f];
                a[0] += z * w.x; a[1] += z * w.y; a[2] += z * w.z; a[3] += z * w.w;
            }
            ((float4*)(sZ2 + r * H2))[c32] =
                make_float4(fmaxf(a[0], 0.f), fmaxf(a[1], 0.f), fmaxf(a[2], 0.f), fmaxf(a[3], 0.f));
        }
        __syncthreads();

        // pred = z2 @ W3 + b3 : [8][12], write transposed out[b][0][p][n]
        if (tid < 96) {
            int r = tid / 12, p = tid % 12;
            float a = sb3[p];
            #pragma unroll 16
            for (int f = 0; f < 128; f++) a += sZ2[r * H2 + f] * sW3[f * NPRED + p];
            int seqr = base + r;
            int bb = seqr >> 11;          // / 2048
            int nn = seqr & 2047;         // % 2048
            out[(size_t)bb * (NPRED * 2048) + p * 2048 + nn] = a;
        }
        __syncthreads();
    }
}

extern "C" void kernel_launch(void* const* d_in, const int* in_sizes, int n_in,
                              void* d_out, int out_size)
{
    const float* x     = (const float*)d_in[0];
    const float* W_in  = (const float*)d_in[1];
    const float* b_in  = (const float*)d_in[2];
    const float* W_c   = (const float*)d_in[3];
    const float* b_c   = (const float*)d_in[4];
    const float* Wq    = (const float*)d_in[5];
    const float* bq    = (const float*)d_in[6];
    const float* Wk    = (const float*)d_in[7];
    const float* bk    = (const float*)d_in[8];
    const float* Wv    = (const float*)d_in[9];
    const float* bv    = (const float*)d_in[10];
    const float* W1    = (const float*)d_in[11];
    const float* b1    = (const float*)d_in[12];
    const float* W2    = (const float*)d_in[13];
    const float* b2    = (const float*)d_in[14];
    const float* W3    = (const float*)d_in[15];
    const float* b3    = (const float*)d_in[16];

    size_t smemA = SMEM_A_FLOATS * sizeof(float);
    size_t smemB = SMEM_B_FLOATS * sizeof(float);
    cudaFuncSetAttribute(kernelA, cudaFuncAttributeMaxDynamicSharedMemorySize, (int)smemA);
    cudaFuncSetAttribute(kernelB, cudaFuncAttributeMaxDynamicSharedMemorySize, (int)smemB);

    kernelA<<<152, 256, smemA>>>(x, W_in, b_in, W_c, b_c, Wq, bq, Wk, bk, Wv, bv);
    kernelB<<<152, 256, smemB>>>(W1, b1, W2, b2, W3, b3, (float*)d_out);
}